// round 1
// baseline (speedup 1.0000x reference)
#include <cuda_runtime.h>
#include <cuda_bf16.h>
#include <cstdint>

#define N_NODES 50000
#define N_EDGES 400000
#define IN_C 128
#define HID 256
#define EDGE_D 32

// ---------------- scratch (device globals; no allocation allowed) ----------
__device__ float g_proj[(size_t)N_NODES * 512];   // [N, 512]: cols 0-255 src-proj, 256-511 dst-proj
__device__ float g_agg [(size_t)N_NODES * 256];
__device__ float g_h   [(size_t)N_NODES * 256];
__device__ float g_h2  [(size_t)N_NODES * 256];
__device__ int   g_deg   [N_NODES];
__device__ int   g_rowptr[N_NODES + 1];
__device__ int   g_cursor[N_NODES];
__device__ int   g_eids  [N_EDGES];

// ---------------- CSR build ------------------------------------------------
__global__ void zero_deg_kernel(int* deg, int n) {
    for (int i = blockIdx.x * blockDim.x + threadIdx.x; i < n; i += gridDim.x * blockDim.x)
        deg[i] = 0;
}

__global__ void count_deg_kernel(const int* __restrict__ dst, int* deg, int e) {
    for (int i = blockIdx.x * blockDim.x + threadIdx.x; i < e; i += gridDim.x * blockDim.x)
        atomicAdd(&deg[dst[i]], 1);
}

// single-block exclusive scan (chunked Hillis-Steele), writes rowptr & cursor
__global__ void scan_kernel(const int* __restrict__ deg, int* rowptr, int* cursor, int n) {
    __shared__ int s[1024];
    __shared__ int carry;
    int tid = threadIdx.x;
    if (tid == 0) { carry = 0; rowptr[0] = 0; }
    __syncthreads();
    for (int base = 0; base < n; base += 1024) {
        int i = base + tid;
        int v = (i < n) ? deg[i] : 0;
        s[tid] = v;
        __syncthreads();
        #pragma unroll
        for (int off = 1; off < 1024; off <<= 1) {
            int t = (tid >= off) ? s[tid - off] : 0;
            __syncthreads();
            s[tid] += t;
            __syncthreads();
        }
        int inc = s[tid] + carry;
        if (i < n) { rowptr[i + 1] = inc; cursor[i] = inc - v; }
        __syncthreads();
        if (tid == 1023) carry = inc;
        __syncthreads();
    }
}

__global__ void scatter_kernel(const int* __restrict__ dst, int* cursor, int* eids, int e) {
    for (int i = blockIdx.x * blockDim.x + threadIdx.x; i < e; i += gridDim.x * blockDim.x) {
        int p = atomicAdd(&cursor[dst[i]], 1);
        eids[p] = i;
    }
}

// ---------------- GEMM: C = act(bias + A1@B1 + A2@B2) ----------------------
// A row-major [M,K] (ld = K), B row-major [K,256] (ld = 256), C ld = ldc.
#define BM 128
#define BN 128
#define BK 8

__global__ __launch_bounds__(256) void gemm_kernel(
    const float* __restrict__ A1, int K1, const float* __restrict__ B1,
    const float* __restrict__ A2, int K2, const float* __restrict__ B2,
    const float* __restrict__ bias, int relu_flag,
    float* __restrict__ C, int ldc, int M, int N)
{
    __shared__ float As[BK][BM];
    __shared__ float Bs[BK][BN];

    int tid = threadIdx.x;
    int tx = tid & 15, ty = tid >> 4;
    int bm = blockIdx.x * BM, bn = blockIdx.y * BN;

    float acc[8][8];
    #pragma unroll
    for (int i = 0; i < 8; i++)
        #pragma unroll
        for (int j = 0; j < 8; j++) acc[i][j] = 0.f;

    int a_row = tid >> 1;          // 0..127
    int a_k   = (tid & 1) * 4;     // 0 or 4
    int b_k   = tid >> 5;          // 0..7
    int b_col = (tid & 31) * 4;    // 0..124

    for (int seg = 0; seg < 2; ++seg) {
        const float* A = (seg == 0) ? A1 : A2;
        const float* B = (seg == 0) ? B1 : B2;
        int K = (seg == 0) ? K1 : K2;
        if (A == nullptr || K == 0) continue;

        for (int k0 = 0; k0 < K; k0 += BK) {
            // load A tile (transposed into smem)
            int gr = bm + a_row;
            float4 av = make_float4(0.f, 0.f, 0.f, 0.f);
            if (gr < M) av = *(const float4*)(A + (size_t)gr * K + k0 + a_k);
            As[a_k + 0][a_row] = av.x;
            As[a_k + 1][a_row] = av.y;
            As[a_k + 2][a_row] = av.z;
            As[a_k + 3][a_row] = av.w;
            // load B tile (direct copy)
            float4 bv = *(const float4*)(B + (size_t)(k0 + b_k) * 256 + bn + b_col);
            *(float4*)&Bs[b_k][b_col] = bv;
            __syncthreads();

            #pragma unroll
            for (int k = 0; k < BK; k++) {
                float af[8], bf[8];
                *(float4*)(af)     = *(const float4*)&As[k][ty * 4];
                *(float4*)(af + 4) = *(const float4*)&As[k][64 + ty * 4];
                *(float4*)(bf)     = *(const float4*)&Bs[k][tx * 4];
                *(float4*)(bf + 4) = *(const float4*)&Bs[k][64 + tx * 4];
                #pragma unroll
                for (int i = 0; i < 8; i++)
                    #pragma unroll
                    for (int j = 0; j < 8; j++)
                        acc[i][j] += af[i] * bf[j];
            }
            __syncthreads();
        }
    }

    // epilogue
    #pragma unroll
    for (int i = 0; i < 8; i++) {
        int r = bm + ((i < 4) ? (ty * 4 + i) : (64 + ty * 4 + i - 4));
        if (r >= M) continue;
        float v[8];
        #pragma unroll
        for (int j = 0; j < 8; j++) {
            int c = (j < 4) ? (tx * 4 + j) : (64 + tx * 4 + j - 4);
            float t = acc[i][j];
            if (bias) t += bias[bn + c];
            if (relu_flag) t = fmaxf(t, 0.f);
            v[j] = t;
        }
        *(float4*)(C + (size_t)r * ldc + bn + tx * 4)      = make_float4(v[0], v[1], v[2], v[3]);
        *(float4*)(C + (size_t)r * ldc + bn + 64 + tx * 4) = make_float4(v[4], v[5], v[6], v[7]);
    }
}

// ---------------- edge aggregation (CSR, per-node, no atomics) -------------
// agg[n,c] = mean_e relu(proj[src_e, c] + proj[n, 256+c] + edge_attr[e]@we[:,c] + eb[c])
__global__ __launch_bounds__(256) void agg_kernel(
    const float* __restrict__ proj,       // [N, 512]
    const float* __restrict__ edge_attr,  // [E, 32]
    const int*   __restrict__ src,
    const int*   __restrict__ rowptr,
    const int*   __restrict__ eids,
    const float* __restrict__ we,         // [32, 256]
    const float* __restrict__ eb,         // [256]
    float* __restrict__ agg, int n)
{
    __shared__ float s_we[32 * 256];
    __shared__ float s_eb[256];
    __shared__ float s_ea[32];

    int tid = threadIdx.x;  // channel
    for (int i = tid; i < 32 * 256; i += 256) s_we[i] = we[i];
    s_eb[tid] = eb[tid];
    __syncthreads();

    float biasc = s_eb[tid];

    for (int node = blockIdx.x; node < n; node += gridDim.x) {
        int beg = rowptr[node], end = rowptr[node + 1];
        float bdst = proj[(size_t)node * 512 + 256 + tid];
        float acc = 0.f;
        for (int p = beg; p < end; ++p) {
            int e = eids[p];
            __syncthreads();
            if (tid < 32) s_ea[tid] = edge_attr[(size_t)e * 32 + tid];
            __syncthreads();
            float v = proj[(size_t)src[e] * 512 + tid] + bdst + biasc;
            #pragma unroll
            for (int d = 0; d < 32; ++d)
                v += s_ea[d] * s_we[d * 256 + tid];
            acc += fmaxf(v, 0.f);
        }
        float denom = (end > beg) ? (float)(end - beg) : 1.f;
        agg[(size_t)node * 256 + tid] = acc / denom;
    }
}

// ---------------- final head: out[n] = h2[n,:]@w + b -----------------------
__global__ void head2_kernel(const float* __restrict__ h,
                             const float* __restrict__ w,
                             const float* __restrict__ b,
                             float* __restrict__ out, int n)
{
    int warp = (blockIdx.x * blockDim.x + threadIdx.x) >> 5;
    int lane = threadIdx.x & 31;
    if (warp >= n) return;
    float s = 0.f;
    #pragma unroll
    for (int c = lane; c < 256; c += 32)
        s += h[(size_t)warp * 256 + c] * w[c];
    #pragma unroll
    for (int off = 16; off; off >>= 1) s += __shfl_xor_sync(0xFFFFFFFFu, s, off);
    if (lane == 0) out[warp] = s + b[0];
}

// ---------------- launch ---------------------------------------------------
extern "C" void kernel_launch(void* const* d_in, const int* in_sizes, int n_in,
                              void* d_out, int out_size)
{
    const float* x   = (const float*)d_in[0];
    const int*   ei  = (const int*)  d_in[1];
    const float* ea  = (const float*)d_in[2];
    const float* e0w = (const float*)d_in[3];
    const float* e0b = (const float*)d_in[4];
    const float* n0w = (const float*)d_in[5];
    const float* n0b = (const float*)d_in[6];
    const float* ew  = (const float*)d_in[7];   // [2, 544, 256]
    const float* ebb = (const float*)d_in[8];   // [2, 256]
    const float* nw  = (const float*)d_in[9];   // [2, 512, 256]
    const float* nb  = (const float*)d_in[10];  // [2, 256]
    const float* h1w = (const float*)d_in[11];
    const float* h1b = (const float*)d_in[12];
    const float* h2w = (const float*)d_in[13];
    const float* h2b = (const float*)d_in[14];
    float* out = (float*)d_out;

    float *proj, *agg, *h, *h2;
    int *deg, *rowptr, *cursor, *eids;
    cudaGetSymbolAddress((void**)&proj,   g_proj);
    cudaGetSymbolAddress((void**)&agg,    g_agg);
    cudaGetSymbolAddress((void**)&h,      g_h);
    cudaGetSymbolAddress((void**)&h2,     g_h2);
    cudaGetSymbolAddress((void**)&deg,    g_deg);
    cudaGetSymbolAddress((void**)&rowptr, g_rowptr);
    cudaGetSymbolAddress((void**)&cursor, g_cursor);
    cudaGetSymbolAddress((void**)&eids,   g_eids);

    const int* src = ei;
    const int* dst = ei + N_EDGES;

    // --- CSR build (once, reused for all 3 layers) ---
    zero_deg_kernel<<<200, 256>>>(deg, N_NODES);
    count_deg_kernel<<<1024, 256>>>(dst, deg, N_EDGES);
    scan_kernel<<<1, 1024>>>(deg, rowptr, cursor, N_NODES);
    scatter_kernel<<<1024, 256>>>(dst, cursor, eids, N_EDGES);

    dim3 gemm_grid((N_NODES + BM - 1) / BM, 256 / BN);
    const int AGG_BLOCKS = 888;

    // ---------- layer 0 ----------
    // projections: proj[:,0:256] = x@e0w[0:128], proj[:,256:512] = x@e0w[128:256]
    gemm_kernel<<<gemm_grid, 256>>>(x, IN_C, e0w,
                                    nullptr, 0, nullptr,
                                    nullptr, 0, proj, 512, N_NODES, 256);
    gemm_kernel<<<gemm_grid, 256>>>(x, IN_C, e0w + (size_t)IN_C * 256,
                                    nullptr, 0, nullptr,
                                    nullptr, 0, proj + 256, 512, N_NODES, 256);
    agg_kernel<<<AGG_BLOCKS, 256>>>(proj, ea, src, rowptr, eids,
                                    e0w + (size_t)2 * IN_C * 256, e0b, agg, N_NODES);
    // node update: h = relu(x@n0w[0:128] + agg@n0w[128:384] + n0b)
    gemm_kernel<<<gemm_grid, 256>>>(x, IN_C, n0w,
                                    agg, HID, n0w + (size_t)IN_C * 256,
                                    n0b, 1, h, 256, N_NODES, 256);

    // ---------- layers 1..2 ----------
    float* h_cur = h;
    float* h_nxt = h2;
    for (int i = 0; i < 2; ++i) {
        const float* ewi = ew + (size_t)i * 544 * 256;
        const float* ebi = ebb + (size_t)i * 256;
        const float* nwi = nw + (size_t)i * 512 * 256;
        const float* nbi = nb + (size_t)i * 256;
        gemm_kernel<<<gemm_grid, 256>>>(h_cur, HID, ewi,
                                        nullptr, 0, nullptr,
                                        nullptr, 0, proj, 512, N_NODES, 256);
        gemm_kernel<<<gemm_grid, 256>>>(h_cur, HID, ewi + (size_t)HID * 256,
                                        nullptr, 0, nullptr,
                                        nullptr, 0, proj + 256, 512, N_NODES, 256);
        agg_kernel<<<AGG_BLOCKS, 256>>>(proj, ea, src, rowptr, eids,
                                        ewi + (size_t)2 * HID * 256, ebi, agg, N_NODES);
        gemm_kernel<<<gemm_grid, 256>>>(h_cur, HID, nwi,
                                        agg, HID, nwi + (size_t)HID * 256,
                                        nbi, 1, h_nxt, 256, N_NODES, 256);
        float* t = h_cur; h_cur = h_nxt; h_nxt = t;
    }

    // ---------- head ----------
    // h_head = relu(h_cur @ h1w + h1b)  -> store into h_nxt
    gemm_kernel<<<gemm_grid, 256>>>(h_cur, HID, h1w,
                                    nullptr, 0, nullptr,
                                    h1b, 1, h_nxt, 256, N_NODES, 256);
    // out = h_head @ h2w + h2b
    head2_kernel<<<(N_NODES * 32 + 255) / 256, 256>>>(h_nxt, h2w, h2b, out, N_NODES);
}

// round 3
// speedup vs baseline: 2.5697x; 2.5697x over previous
#include <cuda_runtime.h>
#include <cuda_bf16.h>
#include <cstdint>

#define N_NODES 50000
#define N_EDGES 400000
#define IN_C 128
#define HID 256

// ---------------- scratch (device globals) ---------------------------------
__device__ float g_proj [(size_t)N_NODES * 512];   // cols 0-255 src-proj, 256-511 dst-proj
__device__ float g_agg  [(size_t)N_NODES * 256];
__device__ float g_h    [(size_t)N_NODES * 256];
__device__ float g_h2   [(size_t)N_NODES * 256];
__device__ float g_eproj[(size_t)N_EDGES * 256];   // per-edge attr projection (+bias), CSR order
__device__ float g_eaperm[(size_t)N_EDGES * 32];   // edge_attr permuted to CSR order
__device__ int g_srcperm[N_EDGES];
__device__ int g_deg[N_NODES], g_rowptr[N_NODES + 1], g_cursor[N_NODES], g_eids[N_EDGES];

// ---------------- CSR build ------------------------------------------------
__global__ void zero_deg_kernel(int* deg, int n) {
    for (int i = blockIdx.x * blockDim.x + threadIdx.x; i < n; i += gridDim.x * blockDim.x)
        deg[i] = 0;
}
__global__ void count_deg_kernel(const int* __restrict__ dst, int* deg, int e) {
    for (int i = blockIdx.x * blockDim.x + threadIdx.x; i < e; i += gridDim.x * blockDim.x)
        atomicAdd(&deg[dst[i]], 1);
}
__global__ void scan_kernel(const int* __restrict__ deg, int* rowptr, int* cursor, int n) {
    __shared__ int s[1024];
    __shared__ int carry;
    int tid = threadIdx.x;
    if (tid == 0) { carry = 0; rowptr[0] = 0; }
    __syncthreads();
    for (int base = 0; base < n; base += 1024) {
        int i = base + tid;
        int v = (i < n) ? deg[i] : 0;
        s[tid] = v;
        __syncthreads();
        #pragma unroll
        for (int off = 1; off < 1024; off <<= 1) {
            int t = (tid >= off) ? s[tid - off] : 0;
            __syncthreads();
            s[tid] += t;
            __syncthreads();
        }
        int inc = s[tid] + carry;
        if (i < n) { rowptr[i + 1] = inc; cursor[i] = inc - v; }
        __syncthreads();
        if (tid == 1023) carry = inc;
        __syncthreads();
    }
}
__global__ void scatter_kernel(const int* __restrict__ dst, int* cursor, int* eids, int e) {
    for (int i = blockIdx.x * blockDim.x + threadIdx.x; i < e; i += gridDim.x * blockDim.x) {
        int p = atomicAdd(&cursor[dst[i]], 1);
        eids[p] = i;
    }
}

// ---------------- permute edge_attr + src into CSR order -------------------
__global__ void permute_ea_kernel(const float* __restrict__ ea, const int* __restrict__ eids,
                                  float* __restrict__ ea_perm, int e) {
    // 8 float4 per edge row (32 floats)
    int total = e * 8;
    for (int g = blockIdx.x * blockDim.x + threadIdx.x; g < total; g += gridDim.x * blockDim.x) {
        int p = g >> 3, q = (g & 7) << 2;
        int src_e = eids[p];
        *(float4*)(ea_perm + (size_t)p * 32 + q) = *(const float4*)(ea + (size_t)src_e * 32 + q);
    }
}
__global__ void permute_src_kernel(const int* __restrict__ src, const int* __restrict__ eids,
                                   int* __restrict__ src_perm, int e) {
    for (int i = blockIdx.x * blockDim.x + threadIdx.x; i < e; i += gridDim.x * blockDim.x)
        src_perm[i] = src[eids[i]];
}

// ---------------- tf32 helpers ---------------------------------------------
__device__ __forceinline__ uint32_t f2tf32(float f) {
    uint32_t r;
    asm("cvt.rna.tf32.f32 %0, %1;" : "=r"(r) : "f"(f));
    return r;
}
__device__ __forceinline__ void mma_tf32(float* c, const uint32_t* a, const uint32_t* b) {
    asm volatile(
        "mma.sync.aligned.m16n8k8.row.col.f32.tf32.tf32.f32 "
        "{%0,%1,%2,%3}, {%4,%5,%6,%7}, {%8,%9}, {%0,%1,%2,%3};"
        : "+f"(c[0]), "+f"(c[1]), "+f"(c[2]), "+f"(c[3])
        : "r"(a[0]), "r"(a[1]), "r"(a[2]), "r"(a[3]), "r"(b[0]), "r"(b[1]));
}

// ---------------- tensor-core GEMM: C = act(bias + A1@B1 + A2@B2) ----------
// A row-major [M,K] fp32; B row-major [K,256] fp32 (original weight layout).
// CTA tile 128(M) x 128(N); grid.y in {0,1} selects the N-half.
// C written at C[row*ldc + col_off + n].
#define PAD_A 36
#define PAD_B 136

__global__ __launch_bounds__(256, 2) void gemm_tc(
    const float* __restrict__ A1, int K1, const float* __restrict__ B1,
    const float* __restrict__ A2, int K2, const float* __restrict__ B2,
    const float* __restrict__ bias, int relu_flag,
    float* __restrict__ C, int ldc, int col_off, int M)
{
    __shared__ uint32_t sA[128 * PAD_A];
    __shared__ uint32_t sB[32 * PAD_B];

    int tid = threadIdx.x, wid = tid >> 5, lane = tid & 31;
    int bm = blockIdx.x * 128;
    int bn = blockIdx.y * 128;
    int wm = (wid >> 2) * 64;       // 0 or 64
    int wn = (wid & 3) * 32;        // 0,32,64,96
    int gq = lane >> 2;             // groupID
    int tq = lane & 3;              // threadID in group

    float acc[4][4][4];
    #pragma unroll
    for (int mi = 0; mi < 4; mi++)
        #pragma unroll
        for (int ni = 0; ni < 4; ni++)
            #pragma unroll
            for (int q = 0; q < 4; q++) acc[mi][ni][q] = 0.f;

    #pragma unroll 1
    for (int seg = 0; seg < 2; ++seg) {
        const float* A = seg ? A2 : A1;
        const float* B = seg ? B2 : B1;
        int K = seg ? K2 : K1;
        if (A == nullptr || K == 0) continue;

        #pragma unroll 1
        for (int k0 = 0; k0 < K; k0 += 32) {
            __syncthreads();
            // stage A [128][32] -> sA (tf32), 1024 float4 groups
            #pragma unroll
            for (int it = 0; it < 4; ++it) {
                int g = tid + it * 256;
                int row = g >> 3, c4 = (g & 7) << 2;
                int grow = bm + row;
                float4 v = make_float4(0.f, 0.f, 0.f, 0.f);
                if (grow < M) v = *(const float4*)(A + (size_t)grow * K + k0 + c4);
                uint32_t* d = &sA[row * PAD_A + c4];
                d[0] = f2tf32(v.x); d[1] = f2tf32(v.y);
                d[2] = f2tf32(v.z); d[3] = f2tf32(v.w);
            }
            // stage B [32][128] -> sB (tf32), 1024 float4 groups
            #pragma unroll
            for (int it = 0; it < 4; ++it) {
                int g = tid + it * 256;
                int row = g >> 5, c4 = (g & 31) << 2;
                float4 v = *(const float4*)(B + (size_t)(k0 + row) * 256 + bn + c4);
                uint32_t* d = &sB[row * PAD_B + c4];
                d[0] = f2tf32(v.x); d[1] = f2tf32(v.y);
                d[2] = f2tf32(v.z); d[3] = f2tf32(v.w);
            }
            __syncthreads();

            #pragma unroll
            for (int ks = 0; ks < 4; ++ks) {
                int kb = ks * 8;
                uint32_t a[4][4], b[4][2];
                #pragma unroll
                for (int mi = 0; mi < 4; mi++) {
                    int r0 = wm + mi * 16 + gq;
                    a[mi][0] = sA[r0 * PAD_A + kb + tq];
                    a[mi][1] = sA[(r0 + 8) * PAD_A + kb + tq];
                    a[mi][2] = sA[r0 * PAD_A + kb + 4 + tq];
                    a[mi][3] = sA[(r0 + 8) * PAD_A + kb + 4 + tq];
                }
                #pragma unroll
                for (int ni = 0; ni < 4; ni++) {
                    int cn = wn + ni * 8 + gq;
                    b[ni][0] = sB[(kb + tq) * PAD_B + cn];
                    b[ni][1] = sB[(kb + 4 + tq) * PAD_B + cn];
                }
                #pragma unroll
                for (int mi = 0; mi < 4; mi++)
                    #pragma unroll
                    for (int ni = 0; ni < 4; ni++)
                        mma_tf32(acc[mi][ni], a[mi], b[ni]);
            }
        }
    }

    // epilogue
    #pragma unroll
    for (int mi = 0; mi < 4; mi++) {
        int r = bm + wm + mi * 16 + gq;
        #pragma unroll
        for (int ni = 0; ni < 4; ni++) {
            int cc = wn + ni * 8 + tq * 2;     // 0..127 within this half
            int gcol = bn + cc;                // 0..255
            float b0 = 0.f, b1 = 0.f;
            if (bias) { b0 = __ldg(bias + gcol); b1 = __ldg(bias + gcol + 1); }
            float v0 = acc[mi][ni][0] + b0, v1 = acc[mi][ni][1] + b1;
            float v2 = acc[mi][ni][2] + b0, v3 = acc[mi][ni][3] + b1;
            if (relu_flag) {
                v0 = fmaxf(v0, 0.f); v1 = fmaxf(v1, 0.f);
                v2 = fmaxf(v2, 0.f); v3 = fmaxf(v3, 0.f);
            }
            if (r < M)     *(float2*)(C + (size_t)r * ldc + col_off + gcol)       = make_float2(v0, v1);
            if (r + 8 < M) *(float2*)(C + (size_t)(r + 8) * ldc + col_off + gcol) = make_float2(v2, v3);
        }
    }
}

// ---------------- edge aggregation (CSR order, sequential eproj) -----------
// agg[n,c] = mean_p relu(proj[src_perm[p], c] + proj[n, 256+c] + eproj[p, c])
__global__ __launch_bounds__(256) void agg_kernel(
    const float* __restrict__ proj, const float* __restrict__ eproj,
    const int* __restrict__ src_perm, const int* __restrict__ rowptr,
    float* __restrict__ agg, int n)
{
    int tid = threadIdx.x;
    for (int node = blockIdx.x; node < n; node += gridDim.x) {
        int beg = rowptr[node], end = rowptr[node + 1];
        float bdst = proj[(size_t)node * 512 + 256 + tid];
        float acc = 0.f;
        int p = beg;
        for (; p + 4 <= end; p += 4) {
            int s0 = src_perm[p],     s1 = src_perm[p + 1];
            int s2 = src_perm[p + 2], s3 = src_perm[p + 3];
            float a0 = proj[(size_t)s0 * 512 + tid] + eproj[(size_t)p * 256 + tid];
            float a1 = proj[(size_t)s1 * 512 + tid] + eproj[(size_t)(p + 1) * 256 + tid];
            float a2 = proj[(size_t)s2 * 512 + tid] + eproj[(size_t)(p + 2) * 256 + tid];
            float a3 = proj[(size_t)s3 * 512 + tid] + eproj[(size_t)(p + 3) * 256 + tid];
            acc += fmaxf(a0 + bdst, 0.f) + fmaxf(a1 + bdst, 0.f)
                 + fmaxf(a2 + bdst, 0.f) + fmaxf(a3 + bdst, 0.f);
        }
        for (; p < end; ++p) {
            float a = proj[(size_t)src_perm[p] * 512 + tid] + eproj[(size_t)p * 256 + tid];
            acc += fmaxf(a + bdst, 0.f);
        }
        agg[(size_t)node * 256 + tid] = acc / fmaxf((float)(end - beg), 1.f);
    }
}

// ---------------- final head -----------------------------------------------
__global__ void head2_kernel(const float* __restrict__ h,
                             const float* __restrict__ w,
                             const float* __restrict__ b,
                             float* __restrict__ out, int n)
{
    int warp = (blockIdx.x * blockDim.x + threadIdx.x) >> 5;
    int lane = threadIdx.x & 31;
    if (warp >= n) return;
    float s = 0.f;
    #pragma unroll
    for (int c = lane; c < 256; c += 32)
        s += h[(size_t)warp * 256 + c] * w[c];
    #pragma unroll
    for (int off = 16; off; off >>= 1) s += __shfl_xor_sync(0xFFFFFFFFu, s, off);
    if (lane == 0) out[warp] = s + b[0];
}

// ---------------- launch ---------------------------------------------------
extern "C" void kernel_launch(void* const* d_in, const int* in_sizes, int n_in,
                              void* d_out, int out_size)
{
    const float* x   = (const float*)d_in[0];
    const int*   ei  = (const int*)  d_in[1];
    const float* ea  = (const float*)d_in[2];
    const float* e0w = (const float*)d_in[3];
    const float* e0b = (const float*)d_in[4];
    const float* n0w = (const float*)d_in[5];
    const float* n0b = (const float*)d_in[6];
    const float* ew  = (const float*)d_in[7];   // [2, 544, 256]
    const float* ebb = (const float*)d_in[8];   // [2, 256]
    const float* nw  = (const float*)d_in[9];   // [2, 512, 256]
    const float* nb  = (const float*)d_in[10];  // [2, 256]
    const float* h1w = (const float*)d_in[11];
    const float* h1b = (const float*)d_in[12];
    const float* h2w = (const float*)d_in[13];
    const float* h2b = (const float*)d_in[14];
    float* out = (float*)d_out;

    float *proj, *agg, *h, *h2, *eproj, *eaperm;
    int *deg, *rowptr, *cursor, *eids, *srcperm;
    cudaGetSymbolAddress((void**)&proj,    g_proj);
    cudaGetSymbolAddress((void**)&agg,     g_agg);
    cudaGetSymbolAddress((void**)&h,       g_h);
    cudaGetSymbolAddress((void**)&h2,      g_h2);
    cudaGetSymbolAddress((void**)&eproj,   g_eproj);
    cudaGetSymbolAddress((void**)&eaperm,  g_eaperm);
    cudaGetSymbolAddress((void**)&srcperm, g_srcperm);
    cudaGetSymbolAddress((void**)&deg,     g_deg);
    cudaGetSymbolAddress((void**)&rowptr,  g_rowptr);
    cudaGetSymbolAddress((void**)&cursor,  g_cursor);
    cudaGetSymbolAddress((void**)&eids,    g_eids);

    const int* src = ei;
    const int* dst = ei + N_EDGES;

    // --- CSR build + permutation (once, reused by all 3 layers) ---
    zero_deg_kernel<<<200, 256>>>(deg, N_NODES);
    count_deg_kernel<<<1024, 256>>>(dst, deg, N_EDGES);
    scan_kernel<<<1, 1024>>>(deg, rowptr, cursor, N_NODES);
    scatter_kernel<<<1024, 256>>>(dst, cursor, eids, N_EDGES);
    permute_ea_kernel<<<2048, 256>>>(ea, eids, eaperm, N_EDGES);
    permute_src_kernel<<<1024, 256>>>(src, eids, srcperm, N_EDGES);

    const int NODE_GRID = (N_NODES + 127) / 128;   // 391
    const int EDGE_GRID = N_EDGES / 128;           // 3125
    const int AGG_BLOCKS = 2048;
    dim3 ngrid(NODE_GRID, 2), egrid(EDGE_GRID, 2);

    // ================= layer 0 =================
    gemm_tc<<<ngrid, 256>>>(x, IN_C, e0w, nullptr, 0, nullptr,
                            nullptr, 0, proj, 512, 0, N_NODES);
    gemm_tc<<<ngrid, 256>>>(x, IN_C, e0w + (size_t)IN_C * 256, nullptr, 0, nullptr,
                            nullptr, 0, proj, 512, 256, N_NODES);
    gemm_tc<<<egrid, 256>>>(eaperm, 32, e0w + (size_t)2 * IN_C * 256, nullptr, 0, nullptr,
                            e0b, 0, eproj, 256, 0, N_EDGES);
    agg_kernel<<<AGG_BLOCKS, 256>>>(proj, eproj, srcperm, rowptr, agg, N_NODES);
    gemm_tc<<<ngrid, 256>>>(x, IN_C, n0w, agg, HID, n0w + (size_t)IN_C * 256,
                            n0b, 1, h, 256, 0, N_NODES);

    // ================= layers 1..2 =================
    float* h_cur = h;
    float* h_nxt = h2;
    for (int i = 0; i < 2; ++i) {
        const float* ewi = ew + (size_t)i * 544 * 256;
        const float* ebi = ebb + (size_t)i * 256;
        const float* nwi = nw + (size_t)i * 512 * 256;
        const float* nbi = nb + (size_t)i * 256;

        gemm_tc<<<ngrid, 256>>>(h_cur, HID, ewi, nullptr, 0, nullptr,
                                nullptr, 0, proj, 512, 0, N_NODES);
        gemm_tc<<<ngrid, 256>>>(h_cur, HID, ewi + (size_t)HID * 256, nullptr, 0, nullptr,
                                nullptr, 0, proj, 512, 256, N_NODES);
        gemm_tc<<<egrid, 256>>>(eaperm, 32, ewi + (size_t)2 * HID * 256, nullptr, 0, nullptr,
                                ebi, 0, eproj, 256, 0, N_EDGES);
        agg_kernel<<<AGG_BLOCKS, 256>>>(proj, eproj, srcperm, rowptr, agg, N_NODES);
        gemm_tc<<<ngrid, 256>>>(h_cur, HID, nwi, agg, HID, nwi + (size_t)HID * 256,
                                nbi, 1, h_nxt, 256, 0, N_NODES);
        float* t = h_cur; h_cur = h_nxt; h_nxt = t;
    }

    // ================= head =================
    gemm_tc<<<ngrid, 256>>>(h_cur, HID, h1w, nullptr, 0, nullptr,
                            h1b, 1, h_nxt, 256, 0, N_NODES);
    head2_kernel<<<(N_NODES * 32 + 255) / 256, 256>>>(h_nxt, h2w, h2b, out, N_NODES);
}